// round 5
// baseline (speedup 1.0000x reference)
#include <cuda_runtime.h>
#include <math.h>

#define S 8192
#define D 2048
#define WSTRIDE 4096           // W row stride (2*D)
#define NCTA_REC 128
#define ROWS_PER_CTA 16        // D / NCTA_REC
#define NCHUNK 64
#define CHUNK 128              // S / NCHUNK
#define REC_THREADS 512

typedef unsigned long long ull;

// ---- scratch (no runtime allocation allowed) ----
__device__ float g_hc[(size_t)S * D];        // cummax result
__device__ float g_cp[(size_t)S * D];        // ctx_proj result
__device__ float g_chunkmax[NCHUNK * D];     // cummax phase-B scratch
__device__ int   g_cnt[S];                   // per-step completion counter (0..128)

#define NEG_INF __int_as_float(0xff800000)

// ---- packed f32x2 helpers ----
__device__ __forceinline__ ull ffma2(ull a, ull b, ull c) {
    ull d;
    asm("fma.rn.f32x2 %0, %1, %2, %3;" : "=l"(d) : "l"(a), "l"(b), "l"(c));
    return d;
}
__device__ __forceinline__ ull pack2(unsigned int lo, unsigned int hi) {
    ull v;
    asm("mov.b64 %0, {%1, %2};" : "=l"(v) : "r"(lo), "r"(hi));
    return v;
}
__device__ __forceinline__ ull pack2f(float x, float y) {
    ull v;
    asm("mov.b64 %0, {%1, %2};" : "=l"(v) : "f"(x), "f"(y));
    return v;
}
__device__ __forceinline__ ull dup2f(float x) {
    ull v;
    asm("mov.b64 %0, {%1, %1};" : "=l"(v) : "f"(x));
    return v;
}
__device__ __forceinline__ float2 unpack2(ull v) {
    float2 r;
    asm("mov.b64 {%0, %1}, %2;" : "=f"(r.x), "=f"(r.y) : "l"(v));
    return r;
}

// ---- fence-free acquire/release primitives ----
__device__ __forceinline__ int ld_acquire_gpu(const int* p) {
    int v;
    asm volatile("ld.acquire.gpu.global.s32 %0, [%1];" : "=r"(v) : "l"(p) : "memory");
    return v;
}
__device__ __forceinline__ void red_release_gpu_add(int* p, int v) {
    asm volatile("red.release.gpu.global.add.s32 [%0], %1;" :: "l"(p), "r"(v) : "memory");
}

// ============================================================
// counter reset (graph replays must start from zeroed counters)
// ============================================================
__global__ void zero_flags_kernel() {
    int idx = blockIdx.x * blockDim.x + threadIdx.x;
    if (idx < S) g_cnt[idx] = 0;
}

// ============================================================
// cummax phase A: per-(chunk, col) max
// ============================================================
__global__ void cummax_chunk_kernel(const float* __restrict__ ce) {
    int col = blockIdx.x * blockDim.x + threadIdx.x;
    int chunk = blockIdx.y;
    const float* p = ce + (size_t)chunk * CHUNK * D + col;
    float m = NEG_INF;
#pragma unroll 8
    for (int r = 0; r < CHUNK; r++) {
        m = fmaxf(m, p[(size_t)r * D]);
    }
    g_chunkmax[chunk * D + col] = m;
}

// ============================================================
// cummax phase B: exclusive prefix-max over chunks, per column
// ============================================================
__global__ void cummax_scan_kernel() {
    int col = blockIdx.x * blockDim.x + threadIdx.x;
    float run = NEG_INF;
    for (int ch = 0; ch < NCHUNK; ch++) {
        float v = g_chunkmax[ch * D + col];
        g_chunkmax[ch * D + col] = run;   // exclusive prefix
        run = fmaxf(run, v);
    }
}

// ============================================================
// cummax phase C: inclusive scan within chunk seeded by prefix
// ============================================================
__global__ void cummax_write_kernel(const float* __restrict__ ce) {
    int col = blockIdx.x * blockDim.x + threadIdx.x;
    int chunk = blockIdx.y;
    float m = g_chunkmax[chunk * D + col];
    const float* p = ce + (size_t)chunk * CHUNK * D + col;
    float*       q = g_hc + (size_t)chunk * CHUNK * D + col;
#pragma unroll 8
    for (int r = 0; r < CHUNK; r++) {
        m = fmaxf(m, p[(size_t)r * D]);
        q[(size_t)r * D] = m;
    }
}

// ============================================================
// GEMM: g_cp[t][i] = sum_j ce[t][j] * W[i][D + j] + b[i]
// f32x2 packed FFMA: accumulators are (n, n+1) pairs.
// ============================================================
#define GT 128
#define GI 128
#define GK 8
#define GPAD 4

__global__ __launch_bounds__(256) void gemm_ctx_kernel(
    const float* __restrict__ A,
    const float* __restrict__ W,
    const float* __restrict__ bias)
{
    __shared__ float As[GK][GT + GPAD];
    __shared__ float Bs[GK][GI + GPAD];

    int tid = threadIdx.x;
    int tx = tid & 15;
    int ty = tid >> 4;
    int i0 = blockIdx.x * GI;
    int t0 = blockIdx.y * GT;

    int lr = tid >> 1;
    int lk = (tid & 1) * 4;

    const float* Ap = A + (size_t)(t0 + lr) * D + lk;
    const float* Bp = W + (size_t)(i0 + lr) * WSTRIDE + D + lk;

    ull acc[8][4];
#pragma unroll
    for (int m = 0; m < 8; m++)
#pragma unroll
        for (int n = 0; n < 4; n++) acc[m][n] = 0ULL;

    float4 ra = *(const float4*)Ap;
    float4 rb = *(const float4*)Bp;

    for (int kk = 0; kk < D; kk += GK) {
        As[lk + 0][lr] = ra.x; As[lk + 1][lr] = ra.y;
        As[lk + 2][lr] = ra.z; As[lk + 3][lr] = ra.w;
        Bs[lk + 0][lr] = rb.x; Bs[lk + 1][lr] = rb.y;
        Bs[lk + 2][lr] = rb.z; Bs[lk + 3][lr] = rb.w;
        __syncthreads();

        if (kk + GK < D) {
            ra = *(const float4*)(Ap + kk + GK);
            rb = *(const float4*)(Bp + kk + GK);
        }

#pragma unroll
        for (int k = 0; k < GK; k++) {
            float4 a0 = *(const float4*)&As[k][ty * 8];
            float4 a1 = *(const float4*)&As[k][ty * 8 + 4];
            float4 b0 = *(const float4*)&Bs[k][tx * 8];
            float4 b1 = *(const float4*)&Bs[k][tx * 8 + 4];
            ull bp[4] = {pack2f(b0.x, b0.y), pack2f(b0.z, b0.w),
                         pack2f(b1.x, b1.y), pack2f(b1.z, b1.w)};
            ull ad[8] = {dup2f(a0.x), dup2f(a0.y), dup2f(a0.z), dup2f(a0.w),
                         dup2f(a1.x), dup2f(a1.y), dup2f(a1.z), dup2f(a1.w)};
#pragma unroll
            for (int m = 0; m < 8; m++)
#pragma unroll
                for (int n = 0; n < 4; n++)
                    acc[m][n] = ffma2(ad[m], bp[n], acc[m][n]);
        }
        __syncthreads();
    }

    float bv[8];
#pragma unroll
    for (int n = 0; n < 8; n++) bv[n] = bias[i0 + tx * 8 + n];

#pragma unroll
    for (int m = 0; m < 8; m++) {
        size_t row = (size_t)(t0 + ty * 8 + m) * D + i0 + tx * 8;
        float2 c0 = unpack2(acc[m][0]), c1 = unpack2(acc[m][1]);
        float2 c2 = unpack2(acc[m][2]), c3 = unpack2(acc[m][3]);
        float4 o0 = make_float4(c0.x + bv[0], c0.y + bv[1],
                                c1.x + bv[2], c1.y + bv[3]);
        float4 o1 = make_float4(c2.x + bv[4], c2.y + bv[5],
                                c3.x + bv[6], c3.y + bv[7]);
        *(float4*)&g_cp[row]     = o0;
        *(float4*)&g_cp[row + 4] = o1;
    }
}

// ============================================================
// Recurrence v4: 128 CTAs x 512 threads (16 warps).
// Warp w owns output row i0+w entirely; lane covers 4 x 16-col groups
// (cols j*512 + lane*16 .. +15, j=0..3). W row slice (64 floats) in regs.
// State: plain (L1-cached) loads of row t-1 — each line is fresh per
// launch and read only after publication, so L1 cannot be stale; the
// 16-warp duplication hits L1, keeping chip L2 traffic at 1 MB/step.
// Row sum: intra-warp shuffle only. No smem, no finalize stage.
// Sync: tid0 acquire-polls g_cnt[t-1] -> bar; bar -> one release-add.
// ============================================================
__global__ __launch_bounds__(REC_THREADS, 1) void recurrence_kernel(
    const float* __restrict__ W,
    float* out)
{
    int tid  = threadIdx.x;
    int lane = tid & 31;
    int w    = tid >> 5;          // warp = row within CTA slice
    int cta  = blockIdx.x;
    int row  = cta * ROWS_PER_CTA + w;

    // ---- preload W row slice: 4 chunks x 16 cols, as f32x2 pairs ----
    ull wreg[32];
    {
        const float* wp = W + (size_t)row * WSTRIDE;
#pragma unroll
        for (int j = 0; j < 4; j++) {
            const float* p = wp + j * 512 + lane * 16;
#pragma unroll
            for (int q = 0; q < 4; q++) {
                uint4 v = *(const uint4*)(p + q * 4);
                wreg[j * 8 + q * 2 + 0] = pack2(v.x, v.y);
                wreg[j * 8 + q * 2 + 1] = pack2(v.z, v.w);
            }
        }
    }

    const ull m1 = dup2f(-1.0f);

    for (int t = 0; t < S; t++) {
        // per-row hc/cp prefetch (in flight during poll/bar)
        float hcv = 0.0f, cpv = 0.0f;
        if (lane == 0) {
            hcv = __ldg(&g_hc[(size_t)t * D + row]);
            cpv = __ldg(&g_cp[(size_t)t * D + row]);
        }

        // ---- wait for row t-1 to be fully published ----
        if (t > 0 && tid == 0) {
            while (ld_acquire_gpu(&g_cnt[t - 1]) < NCTA_REC) { }
        }
        __syncthreads();

        // ---- partial dot: 64 cols/lane, packed f32x2 ----
        ull a0 = 0, a1 = 0, a2 = 0, a3 = 0;
        if (t == 0) {
#pragma unroll
            for (int j = 0; j < 8; j++) {
                a0 = ffma2(wreg[j * 4 + 0], m1, a0);
                a1 = ffma2(wreg[j * 4 + 1], m1, a1);
                a2 = ffma2(wreg[j * 4 + 2], m1, a2);
                a3 = ffma2(wreg[j * 4 + 3], m1, a3);
            }
        } else {
            const float* src = out + (size_t)(t - 1) * D;
#pragma unroll
            for (int j = 0; j < 4; j++) {
                const float* p = src + j * 512 + lane * 16;
                uint4 v0 = *(const uint4*)(p + 0);
                uint4 v1 = *(const uint4*)(p + 4);
                uint4 v2 = *(const uint4*)(p + 8);
                uint4 v3 = *(const uint4*)(p + 12);
                a0 = ffma2(wreg[j * 8 + 0], pack2(v0.x, v0.y), a0);
                a1 = ffma2(wreg[j * 8 + 1], pack2(v0.z, v0.w), a1);
                a2 = ffma2(wreg[j * 8 + 2], pack2(v1.x, v1.y), a2);
                a3 = ffma2(wreg[j * 8 + 3], pack2(v1.z, v1.w), a3);
                a0 = ffma2(wreg[j * 8 + 4], pack2(v2.x, v2.y), a0);
                a1 = ffma2(wreg[j * 8 + 5], pack2(v2.z, v2.w), a1);
                a2 = ffma2(wreg[j * 8 + 6], pack2(v3.x, v3.y), a2);
                a3 = ffma2(wreg[j * 8 + 7], pack2(v3.z, v3.w), a3);
            }
        }
        float2 f0 = unpack2(a0), f1 = unpack2(a1),
               f2 = unpack2(a2), f3 = unpack2(a3);
        float r = (f0.x + f0.y) + (f1.x + f1.y)
                + (f2.x + f2.y) + (f3.x + f3.y);

        // ---- intra-warp reduction: full row sum ----
#pragma unroll
        for (int off = 16; off > 0; off >>= 1)
            r += __shfl_xor_sync(0xFFFFFFFFu, r, off);

        // ---- lane 0 finalizes its row ----
        if (lane == 0) {
            float x  = r + cpv;
            float g  = 1.0f / (1.0f + __expf(-x));
            float ns = hcv * g;
            __stcg(&out[(size_t)t * D + row], ns);
            if (t == S - 1) __stcg(&out[(size_t)S * D + row], ns);
        }
        __syncthreads();   // all 16 rows stored before the CTA's release

        if (tid == 0)
            red_release_gpu_add(&g_cnt[t], 1);   // publish step t
    }
}

// ============================================================
extern "C" void kernel_launch(void* const* d_in, const int* in_sizes, int n_in,
                              void* d_out, int out_size) {
    const float* ce = (const float*)d_in[0];   // (S, D)
    const float* W  = (const float*)d_in[1];   // (D, 2D)
    const float* b  = (const float*)d_in[2];   // (D,)
    float* out = (float*)d_out;                // (S*D + D) floats

    zero_flags_kernel<<<(S + 1023) / 1024, 1024>>>();

    dim3 cgrid(D / 256, NCHUNK);
    cummax_chunk_kernel<<<cgrid, 256>>>(ce);
    cummax_scan_kernel<<<D / 256, 256>>>();
    cummax_write_kernel<<<cgrid, 256>>>(ce);

    dim3 ggrid(D / GI, S / GT);
    gemm_ctx_kernel<<<ggrid, 256>>>(ce, W, b);

    recurrence_kernel<<<NCTA_REC, REC_THREADS>>>(W, out);
}